// round 7
// baseline (speedup 1.0000x reference)
#include <cuda_runtime.h>
#include <cstdint>
#include <math.h>

#define NT 8192
#define DM 2048
#define DH 2048
#define NE 16

#define BM 128
#define BN 128
#define BK 32
#define KTILES (DM / BK)        // 64
#define NSTAGE 4

#define A_BYTES 16384           // 128 rows * 32 tf32 * 4B (128B rows, swizzled)
#define B_BYTES 16384           // 128 n-rows * 32 k * 4B
#define STAGE_BYTES (A_BYTES + B_BYTES)         // 32 KB
#define SMEM_BYTES (NSTAGE * STAGE_BYTES + 1024)

#define SWZ(o) ((unsigned)(o) ^ ((((unsigned)(o)) >> 3) & 0x70))

// ---------------- device scratch (allocation-free) ----------------
__device__ int   g_count[NE];
__device__ int   g_list[NE][NT];                    // token*2 + slot
__device__ float g_gate[NE][NT];
__device__ float g_scratch[(size_t)NT * 2 * DH];    // 128 MB combine scratch
__device__ float g_xr[(size_t)NT * DM];             // 64 MB  rna-tf32 x
__device__ float g_wr[(size_t)NE * DH * DM];        // 256 MB rna-tf32 W, TRANSPOSED [e][n][k]

// ---------------- helpers ----------------
__device__ __forceinline__ unsigned f2tf32(float f) {
    unsigned r;
    asm("cvt.rna.tf32.f32 %0, %1;" : "=r"(r) : "f"(f));
    return r;
}
__device__ __forceinline__ uint32_t smem_u32(const void* p) {
    return (uint32_t)__cvta_generic_to_shared(p);
}
__device__ __forceinline__ void mma_tf32(float& c0, float& c1, float& c2, float& c3,
                                         unsigned a0, unsigned a1, unsigned a2, unsigned a3,
                                         unsigned b0, unsigned b1) {
    asm volatile(
        "mma.sync.aligned.m16n8k8.row.col.f32.tf32.tf32.f32 "
        "{%0,%1,%2,%3}, {%4,%5,%6,%7}, {%8,%9}, {%0,%1,%2,%3};"
        : "+f"(c0), "+f"(c1), "+f"(c2), "+f"(c3)
        : "r"(a0), "r"(a1), "r"(a2), "r"(a3), "r"(b0), "r"(b1));
}
#define LDSM_X4(r0, r1, r2, r3, addr)                                        \
    asm volatile("ldmatrix.sync.aligned.m8n8.x4.shared.b16 {%0,%1,%2,%3}, [%4];" \
        : "=r"(r0), "=r"(r1), "=r"(r2), "=r"(r3) : "r"(addr))

#define CP_ASYNC16(dst, src) \
    asm volatile("cp.async.cg.shared.global [%0], [%1], 16;" :: "r"(dst), "l"(src))
#define CP_COMMIT()  asm volatile("cp.async.commit_group;" ::)
#define CP_WAIT(n)   asm volatile("cp.async.wait_group %0;" :: "n"(n))

// ---------------------------------------------------------------------------
__global__ void zero_counters() {
    if (threadIdx.x < NE) g_count[threadIdx.x] = 0;
}

// ---------------------------------------------------------------------------
// Round W to rna-tf32 AND transpose to [e][n][k] (k contiguous) for ldmatrix
// ---------------------------------------------------------------------------
__global__ void round_transpose_w(const float* __restrict__ w) {
    __shared__ float tile[32][33];
    const int e  = blockIdx.z;
    const int n0 = blockIdx.x * 32;
    const int k0 = blockIdx.y * 32;
    const int tx = threadIdx.x & 31;
    const int ty = threadIdx.x >> 5;   // 0..7

    const float* src = w + ((size_t)e * DM + k0) * DH + n0;
#pragma unroll
    for (int j = 0; j < 4; j++) {
        float v = src[(size_t)(ty + j * 8) * DH + tx];
        tile[ty + j * 8][tx] = __uint_as_float(f2tf32(v));
    }
    __syncthreads();
    float* dst = g_wr + ((size_t)e * DH + n0) * DM + k0;
#pragma unroll
    for (int j = 0; j < 4; j++)
        dst[(size_t)(ty + j * 8) * DM + tx] = tile[tx][ty + j * 8];
}

// ---------------------------------------------------------------------------
// Router: warp per token; also writes rna-tf32 x copy
// ---------------------------------------------------------------------------
__global__ void router_kernel(const float* __restrict__ x,
                              const float* __restrict__ rw) {
    int token = (blockIdx.x * blockDim.x + threadIdx.x) >> 5;
    int lane  = threadIdx.x & 31;
    if (token >= NT) return;

    const float* xr = x + (size_t)token * DM;
    float* xo = g_xr + (size_t)token * DM;
    float acc[NE];
#pragma unroll
    for (int e = 0; e < NE; e++) acc[e] = 0.f;

    for (int i = lane; i < DM; i += 32) {
        float xv = xr[i];
        xo[i] = __uint_as_float(f2tf32(xv));
#pragma unroll
        for (int e = 0; e < NE; e++)
            acc[e] = fmaf(xv, rw[e * DM + i], acc[e]);
    }
#pragma unroll
    for (int off = 16; off > 0; off >>= 1) {
#pragma unroll
        for (int e = 0; e < NE; e++)
            acc[e] += __shfl_xor_sync(0xFFFFFFFFu, acc[e], off);
    }

    if (lane == 0) {
        int i1 = 0; float v1 = acc[0];
#pragma unroll
        for (int e = 1; e < NE; e++)
            if (acc[e] > v1) { v1 = acc[e]; i1 = e; }
        int i2 = -1; float v2 = -3.402823466e38f;
#pragma unroll
        for (int e = 0; e < NE; e++)
            if (e != i1 && acc[e] > v2) { v2 = acc[e]; i2 = e; }

        float t  = expf(v2 - v1);
        float g1 = 1.f / (1.f + t);
        float g2 = t * g1;

        int p1 = atomicAdd(&g_count[i1], 1);
        g_list[i1][p1] = token * 2 + 0; g_gate[i1][p1] = g1;
        int p2 = atomicAdd(&g_count[i2], 1);
        g_list[i2][p2] = token * 2 + 1; g_gate[i2][p2] = g2;
    }
}

// ---------------------------------------------------------------------------
// Gathered per-expert GEMM: 128x128x2048, tf32 mma + ldmatrix, 4-stage cp.async
// 8 warps, warp tile 64(M) x 32(N). No cvt in hot loop (inputs pre-rounded).
// ---------------------------------------------------------------------------
__global__ void __launch_bounds__(256, 1)
moe_gemm_kernel() {
    extern __shared__ char dyn[];
    const uint32_t sbase = (smem_u32(dyn) + 1023u) & ~1023u;

    const int e   = blockIdx.z;
    const int cnt = g_count[e];
    const int m0  = blockIdx.y * BM;
    if (m0 >= cnt) return;
    const int n0  = blockIdx.x * BN;

    const int tid  = threadIdx.x;
    const int lane = tid & 31;
    const int wid  = tid >> 5;
    const int wm   = wid & 1;     // 2 warp-rows (64 M each)
    const int wn   = wid >> 1;    // 4 warp-cols (32 N each)
    const int grp  = lane >> 2;
    const int tg   = lane & 3;

    // ---- cp.async setup: 4 A-chunks + 4 B-chunks (16B) per thread ----
    const float* aSrc[4]; const float* bSrc[4]; uint32_t off[4];
#pragma unroll
    for (int i = 0; i < 4; i++) {
        int v   = tid * 4 + i;          // 0..1023
        int row = v >> 3, c = v & 7;
        int gm  = m0 + row; if (gm >= cnt) gm = cnt - 1;
        int tok = g_list[e][gm] >> 1;
        aSrc[i] = g_xr + (size_t)tok * DM + c * 4;
        bSrc[i] = g_wr + ((size_t)e * DH + n0 + row) * DM + c * 4;
        off[i]  = SWZ(row * 128 + c * 16);
    }

#define LOAD_STAGE(s, kt)                                                    \
    do {                                                                     \
        uint32_t _b = sbase + (uint32_t)(s) * STAGE_BYTES;                   \
        _Pragma("unroll")                                                    \
        for (int i = 0; i < 4; i++)                                          \
            CP_ASYNC16(_b + off[i], aSrc[i] + (kt) * BK);                    \
        _Pragma("unroll")                                                    \
        for (int i = 0; i < 4; i++)                                          \
            CP_ASYNC16(_b + A_BYTES + off[i], bSrc[i] + (kt) * BK);          \
        CP_COMMIT();                                                         \
    } while (0)

    LOAD_STAGE(0, 0);
    LOAD_STAGE(1, 1);
    LOAD_STAGE(2, 2);

    // ---- ldmatrix per-thread geometry ----
    // A x4: mat0 = rows m..+7 k0-3 | mat1 = +8 rows | mat2 = k4-7 | mat3 = +8,k4-7
    const uint32_t key  = lane & 7;
    const uint32_t aRB  = (uint32_t)(wm * 64 + ((lane >> 3) & 1) * 8 + (lane & 7)) * 128;
    const uint32_t aCH  = (lane >> 4) & 1;
    // B x4: mat0 = n..+7 k0-3 | mat1 = n..+7 k4-7 | mat2 = +8 rows k0-3 | mat3 = +8 k4-7
    const uint32_t bRB  = (uint32_t)(wn * 32 + ((lane >> 4) & 1) * 8 + (lane & 7)) * 128;
    const uint32_t bCH  = (lane >> 3) & 1;

    float c[4][4][4];
#pragma unroll
    for (int mb = 0; mb < 4; mb++)
#pragma unroll
        for (int nb = 0; nb < 4; nb++)
#pragma unroll
            for (int j = 0; j < 4; j++) c[mb][nb][j] = 0.f;

    for (int kt = 0; kt < KTILES; kt++) {
        if (kt < KTILES - 2)       CP_WAIT(2);
        else if (kt == KTILES - 2) CP_WAIT(1);
        else                       CP_WAIT(0);
        __syncthreads();

        if (kt + 3 < KTILES) LOAD_STAGE((kt + 3) & 3, kt + 3);

        const uint32_t sA = sbase + (uint32_t)(kt & 3) * STAGE_BYTES;
        const uint32_t sB = sA + A_BYTES;

#pragma unroll
        for (int ks = 0; ks < 4; ks++) {          // 4 k8 steps in BK=32
            const uint32_t ca = ((ks * 2 + aCH) ^ key) << 4;
            const uint32_t cb = ((ks * 2 + bCH) ^ key) << 4;
            unsigned a[4][4];
#pragma unroll
            for (int mb = 0; mb < 4; mb++)
                LDSM_X4(a[mb][0], a[mb][1], a[mb][2], a[mb][3],
                        sA + aRB + mb * 2048 + ca);
            unsigned b[2][4];
#pragma unroll
            for (int nb2 = 0; nb2 < 2; nb2++)
                LDSM_X4(b[nb2][0], b[nb2][1], b[nb2][2], b[nb2][3],
                        sB + bRB + nb2 * 2048 + cb);
#pragma unroll
            for (int mb = 0; mb < 4; mb++)
#pragma unroll
                for (int nb = 0; nb < 4; nb++) {
                    const unsigned b0 = b[nb >> 1][(nb & 1) * 2];
                    const unsigned b1 = b[nb >> 1][(nb & 1) * 2 + 1];
                    mma_tf32(c[mb][nb][0], c[mb][nb][1], c[mb][nb][2], c[mb][nb][3],
                             a[mb][0], a[mb][1], a[mb][2], a[mb][3], b0, b1);
                }
        }
    }
#undef LOAD_STAGE

    // ---- epilogue: gate-scale, STG.64 into disjoint (token,slot) scratch rows ----
#pragma unroll
    for (int mb = 0; mb < 4; mb++) {
#pragma unroll
        for (int half = 0; half < 2; half++) {
            int gm = m0 + wm * 64 + mb * 16 + grp + half * 8;
            if (gm >= cnt) continue;
            int   sl = g_list[e][gm];
            float gt = g_gate[e][gm];
            float* orow = g_scratch + (size_t)sl * DH + n0 + wn * 32;
#pragma unroll
            for (int nb = 0; nb < 4; nb++) {
                int col = nb * 8 + 2 * tg;
                float2 v = make_float2(gt * c[mb][nb][half * 2 + 0],
                                       gt * c[mb][nb][half * 2 + 1]);
                *reinterpret_cast<float2*>(orow + col) = v;
            }
        }
    }
}

// ---------------------------------------------------------------------------
// Combine: out[t] = scratch[2t] + scratch[2t+1]
// ---------------------------------------------------------------------------
__global__ void combine_kernel(float4* __restrict__ out) {
    const int C = DH / 4;
    int i = blockIdx.x * blockDim.x + threadIdx.x;
    int t = i / C, col = i - t * C;
    const float4* s = reinterpret_cast<const float4*>(g_scratch);
    float4 a = s[(size_t)(2 * t) * C + col];
    float4 b = s[(size_t)(2 * t + 1) * C + col];
    out[i] = make_float4(a.x + b.x, a.y + b.y, a.z + b.z, a.w + b.w);
}

// ---------------------------------------------------------------------------
extern "C" void kernel_launch(void* const* d_in, const int* in_sizes, int n_in,
                              void* d_out, int out_size) {
    const float* x  = (const float*)d_in[0];   // [NT, DM]
    const float* rw = (const float*)d_in[1];   // [NE, DM]
    const float* ew = (const float*)d_in[2];   // [NE, DM, DH]
    float* out = (float*)d_out;                // [NT, DH]

    cudaFuncSetAttribute(moe_gemm_kernel,
                         cudaFuncAttributeMaxDynamicSharedMemorySize, SMEM_BYTES);

    zero_counters<<<1, 32>>>();
    {
        dim3 g(DH / 32, DM / 32, NE);          // (64, 64, 16)
        round_transpose_w<<<g, 256>>>(ew);
    }
    router_kernel<<<NT / 8, 256>>>(x, rw);

    dim3 grid(DH / BN, NT / BM, NE);           // (16, 64, 16), early-exit on cnt
    moe_gemm_kernel<<<grid, 256, SMEM_BYTES>>>();

    combine_kernel<<<(NT * DH / 4) / 256, 256>>>((float4*)out);
}

// round 8
// speedup vs baseline: 1.4142x; 1.4142x over previous
#include <cuda_runtime.h>
#include <cstdint>
#include <math.h>

#define NT 8192
#define DM 2048
#define DH 2048
#define NE 16

#define BM 128
#define BN 256
#define BK 32
#define KTILES (DM / BK)        // 64
#define NSTAGE 4

#define A_BYTES 16384           // 128 m-rows * 128 B
#define B_BYTES 32768           // 256 n-rows * 128 B
#define STAGE_BYTES (A_BYTES + B_BYTES)         // 48 KB
#define SMEM_BYTES (NSTAGE * STAGE_BYTES + 1024)

#define SWZ(o) ((unsigned)(o) ^ ((((unsigned)(o)) >> 3) & 0x70))

// ---------------- device scratch (allocation-free) ----------------
__device__ int   g_count[NE];
__device__ int   g_list[NE][NT];                    // token*2 + slot
__device__ float g_gate[NE][NT];
__device__ float g_scratch[(size_t)NT * 2 * DH];    // 128 MB combine scratch
__device__ float g_xr[(size_t)NT * DM];             // 64 MB  rna-tf32 x
__device__ float g_wr[(size_t)NE * DH * DM];        // 256 MB rna-tf32 W, transposed [e][n][k]

// ---------------- helpers ----------------
__device__ __forceinline__ unsigned f2tf32(float f) {
    unsigned r;
    asm("cvt.rna.tf32.f32 %0, %1;" : "=r"(r) : "f"(f));
    return r;
}
__device__ __forceinline__ uint32_t smem_u32(const void* p) {
    return (uint32_t)__cvta_generic_to_shared(p);
}
__device__ __forceinline__ void mma_tf32(float& c0, float& c1, float& c2, float& c3,
                                         unsigned a0, unsigned a1, unsigned a2, unsigned a3,
                                         unsigned b0, unsigned b1) {
    asm volatile(
        "mma.sync.aligned.m16n8k8.row.col.f32.tf32.tf32.f32 "
        "{%0,%1,%2,%3}, {%4,%5,%6,%7}, {%8,%9}, {%0,%1,%2,%3};"
        : "+f"(c0), "+f"(c1), "+f"(c2), "+f"(c3)
        : "r"(a0), "r"(a1), "r"(a2), "r"(a3), "r"(b0), "r"(b1));
}
#define LDSM_X4(r0, r1, r2, r3, addr)                                        \
    asm volatile("ldmatrix.sync.aligned.m8n8.x4.shared.b16 {%0,%1,%2,%3}, [%4];" \
        : "=r"(r0), "=r"(r1), "=r"(r2), "=r"(r3) : "r"(addr))

#define CP_ASYNC16(dst, src) \
    asm volatile("cp.async.cg.shared.global [%0], [%1], 16;" :: "r"(dst), "l"(src))
#define CP_COMMIT()  asm volatile("cp.async.commit_group;" ::)
#define CP_WAIT(n)   asm volatile("cp.async.wait_group %0;" :: "n"(n))

// ---------------------------------------------------------------------------
__global__ void zero_counters() {
    if (threadIdx.x < NE) g_count[threadIdx.x] = 0;
}

// ---------------------------------------------------------------------------
// Round W to rna-tf32 AND transpose to [e][n][k] (k contiguous) for ldmatrix
// ---------------------------------------------------------------------------
__global__ void round_transpose_w(const float* __restrict__ w) {
    __shared__ float tile[32][33];
    const int e  = blockIdx.z;
    const int n0 = blockIdx.x * 32;
    const int k0 = blockIdx.y * 32;
    const int tx = threadIdx.x & 31;
    const int ty = threadIdx.x >> 5;   // 0..7

    const float* src = w + ((size_t)e * DM + k0) * DH + n0;
#pragma unroll
    for (int j = 0; j < 4; j++) {
        float v = src[(size_t)(ty + j * 8) * DH + tx];
        tile[ty + j * 8][tx] = __uint_as_float(f2tf32(v));
    }
    __syncthreads();
    float* dst = g_wr + ((size_t)e * DH + n0) * DM + k0;
#pragma unroll
    for (int j = 0; j < 4; j++)
        dst[(size_t)(ty + j * 8) * DM + tx] = tile[tx][ty + j * 8];
}

// ---------------------------------------------------------------------------
// Router: warp per token; also writes rna-tf32 x copy
// ---------------------------------------------------------------------------
__global__ void router_kernel(const float* __restrict__ x,
                              const float* __restrict__ rw) {
    int token = (blockIdx.x * blockDim.x + threadIdx.x) >> 5;
    int lane  = threadIdx.x & 31;
    if (token >= NT) return;

    const float* xr = x + (size_t)token * DM;
    float* xo = g_xr + (size_t)token * DM;
    float acc[NE];
#pragma unroll
    for (int e = 0; e < NE; e++) acc[e] = 0.f;

    for (int i = lane; i < DM; i += 32) {
        float xv = xr[i];
        xo[i] = __uint_as_float(f2tf32(xv));
#pragma unroll
        for (int e = 0; e < NE; e++)
            acc[e] = fmaf(xv, rw[e * DM + i], acc[e]);
    }
#pragma unroll
    for (int off = 16; off > 0; off >>= 1) {
#pragma unroll
        for (int e = 0; e < NE; e++)
            acc[e] += __shfl_xor_sync(0xFFFFFFFFu, acc[e], off);
    }

    if (lane == 0) {
        int i1 = 0; float v1 = acc[0];
#pragma unroll
        for (int e = 1; e < NE; e++)
            if (acc[e] > v1) { v1 = acc[e]; i1 = e; }
        int i2 = -1; float v2 = -3.402823466e38f;
#pragma unroll
        for (int e = 0; e < NE; e++)
            if (e != i1 && acc[e] > v2) { v2 = acc[e]; i2 = e; }

        float t  = expf(v2 - v1);
        float g1 = 1.f / (1.f + t);
        float g2 = t * g1;

        int p1 = atomicAdd(&g_count[i1], 1);
        g_list[i1][p1] = token * 2 + 0; g_gate[i1][p1] = g1;
        int p2 = atomicAdd(&g_count[i2], 1);
        g_list[i2][p2] = token * 2 + 1; g_gate[i2][p2] = g2;
    }
}

// ---------------------------------------------------------------------------
// Gathered per-expert GEMM: CTA 128x256xK, warp tile 64x64, tf32 mma+ldmatrix,
// 4-stage cp.async, register fragment double-buffering. 8 warps, 1 CTA/SM.
// ---------------------------------------------------------------------------
__global__ void __launch_bounds__(256, 1)
moe_gemm_kernel() {
    extern __shared__ char dyn[];
    const uint32_t sbase = (smem_u32(dyn) + 1023u) & ~1023u;

    const int e   = blockIdx.z;
    const int cnt = g_count[e];
    const int m0  = blockIdx.y * BM;
    if (m0 >= cnt) return;
    const int n0  = blockIdx.x * BN;

    const int tid  = threadIdx.x;
    const int lane = tid & 31;
    const int wid  = tid >> 5;
    const int wm   = wid & 1;     // 2 warp-rows (64 M each)
    const int wn   = wid >> 1;    // 4 warp-cols (64 N each)
    const int grp  = lane >> 2;
    const int tg   = lane & 3;

    // ---- cp.async setup: 4 A-chunks + 8 B-chunks (16B) per thread ----
    // chunk v = tid + 256*i: row = (tid>>3)+32*i, col-chunk c = tid&7 (const)
    const int   rr = tid >> 3;            // 0..31
    const int   cc8 = tid & 7;
    const uint32_t off0 = SWZ(rr * 128 + cc8 * 16);
    const float* aSrc[4];
#pragma unroll
    for (int i = 0; i < 4; i++) {
        int gm = m0 + rr + 32 * i; if (gm >= cnt) gm = cnt - 1;
        int tok = g_list[e][gm] >> 1;
        aSrc[i] = g_xr + (size_t)tok * DM + cc8 * 4;
    }
    const float* bSrc = g_wr + ((size_t)e * DH + n0 + rr) * DM + cc8 * 4;

#define LOAD_STAGE(s, kt)                                                    \
    do {                                                                     \
        uint32_t _b = sbase + (uint32_t)(s) * STAGE_BYTES;                   \
        _Pragma("unroll")                                                    \
        for (int i = 0; i < 4; i++)                                          \
            CP_ASYNC16(_b + off0 + i * 4096u, aSrc[i] + (kt) * BK);          \
        _Pragma("unroll")                                                    \
        for (int i = 0; i < 8; i++)                                          \
            CP_ASYNC16(_b + A_BYTES + off0 + i * 4096u,                      \
                       bSrc + (size_t)i * 32 * DM + (kt) * BK);              \
        CP_COMMIT();                                                         \
    } while (0)

    LOAD_STAGE(0, 0);
    LOAD_STAGE(1, 1);
    LOAD_STAGE(2, 2);

    // ---- ldmatrix per-thread geometry (validated in R7) ----
    const uint32_t key = lane & 7;
    const uint32_t aRB = (uint32_t)(wm * 64 + ((lane >> 3) & 1) * 8 + (lane & 7)) * 128;
    const uint32_t aCH = (lane >> 4) & 1;
    const uint32_t bRB = (uint32_t)(wn * 64 + ((lane >> 4) & 1) * 8 + (lane & 7)) * 128;
    const uint32_t bCH = (lane >> 3) & 1;

    float c[4][8][4];
#pragma unroll
    for (int mb = 0; mb < 4; mb++)
#pragma unroll
        for (int nb = 0; nb < 8; nb++)
#pragma unroll
            for (int j = 0; j < 4; j++) c[mb][nb][j] = 0.f;

    unsigned af[2][4][4];   // [buf][mb][frag]
    unsigned bf[2][4][4];   // [buf][nb2][mat]

#define LOAD_FRAGS(buf, sA, sB, ks)                                          \
    do {                                                                     \
        const uint32_t _ca = (((ks) * 2 + aCH) ^ key) << 4;                  \
        const uint32_t _cb = (((ks) * 2 + bCH) ^ key) << 4;                  \
        _Pragma("unroll")                                                    \
        for (int mb = 0; mb < 4; mb++)                                       \
            LDSM_X4(af[buf][mb][0], af[buf][mb][1], af[buf][mb][2],          \
                    af[buf][mb][3], (sA) + aRB + mb * 2048u + _ca);          \
        _Pragma("unroll")                                                    \
        for (int nb2 = 0; nb2 < 4; nb2++)                                    \
            LDSM_X4(bf[buf][nb2][0], bf[buf][nb2][1], bf[buf][nb2][2],       \
                    bf[buf][nb2][3], (sB) + bRB + nb2 * 2048u + _cb);        \
    } while (0)

#define MMA_FRAGS(buf)                                                       \
    do {                                                                     \
        _Pragma("unroll")                                                    \
        for (int mb = 0; mb < 4; mb++)                                       \
            _Pragma("unroll")                                                \
            for (int nb = 0; nb < 8; nb++) {                                 \
                const unsigned b0 = bf[buf][nb >> 1][(nb & 1) * 2];          \
                const unsigned b1 = bf[buf][nb >> 1][(nb & 1) * 2 + 1];      \
                mma_tf32(c[mb][nb][0], c[mb][nb][1], c[mb][nb][2],           \
                         c[mb][nb][3], af[buf][mb][0], af[buf][mb][1],       \
                         af[buf][mb][2], af[buf][mb][3], b0, b1);            \
            }                                                                \
    } while (0)

    for (int kt = 0; kt < KTILES; kt++) {
        if (kt < KTILES - 2)       CP_WAIT(2);
        else if (kt == KTILES - 2) CP_WAIT(1);
        else                       CP_WAIT(0);
        __syncthreads();

        if (kt + 3 < KTILES) LOAD_STAGE((kt + 3) & 3, kt + 3);

        const uint32_t sA = sbase + (uint32_t)(kt & 3) * STAGE_BYTES;
        const uint32_t sB = sA + A_BYTES;

        LOAD_FRAGS(0, sA, sB, 0);
#pragma unroll
        for (int ks = 0; ks < 4; ks++) {
            if (ks < 3) LOAD_FRAGS((ks + 1) & 1, sA, sB, ks + 1);
            MMA_FRAGS(ks & 1);
        }
    }
#undef LOAD_STAGE
#undef LOAD_FRAGS
#undef MMA_FRAGS

    // ---- epilogue: gate-scale, STG.64 into disjoint (token,slot) scratch rows ----
#pragma unroll
    for (int mb = 0; mb < 4; mb++) {
#pragma unroll
        for (int half = 0; half < 2; half++) {
            int gm = m0 + wm * 64 + mb * 16 + grp + half * 8;
            if (gm >= cnt) continue;
            int   sl = g_list[e][gm];
            float gt = g_gate[e][gm];
            float* orow = g_scratch + (size_t)sl * DH + n0 + wn * 64;
#pragma unroll
            for (int nb = 0; nb < 8; nb++) {
                int col = nb * 8 + 2 * tg;
                float2 v = make_float2(gt * c[mb][nb][half * 2 + 0],
                                       gt * c[mb][nb][half * 2 + 1]);
                *reinterpret_cast<float2*>(orow + col) = v;
            }
        }
    }
}

// ---------------------------------------------------------------------------
// Combine: out[t] = scratch[2t] + scratch[2t+1]
// ---------------------------------------------------------------------------
__global__ void combine_kernel(float4* __restrict__ out) {
    const int C = DH / 4;
    int i = blockIdx.x * blockDim.x + threadIdx.x;
    int t = i / C, col = i - t * C;
    const float4* s = reinterpret_cast<const float4*>(g_scratch);
    float4 a = s[(size_t)(2 * t) * C + col];
    float4 b = s[(size_t)(2 * t + 1) * C + col];
    out[i] = make_float4(a.x + b.x, a.y + b.y, a.z + b.z, a.w + b.w);
}

// ---------------------------------------------------------------------------
extern "C" void kernel_launch(void* const* d_in, const int* in_sizes, int n_in,
                              void* d_out, int out_size) {
    const float* x  = (const float*)d_in[0];   // [NT, DM]
    const float* rw = (const float*)d_in[1];   // [NE, DM]
    const float* ew = (const float*)d_in[2];   // [NE, DM, DH]
    float* out = (float*)d_out;                // [NT, DH]

    cudaFuncSetAttribute(moe_gemm_kernel,
                         cudaFuncAttributeMaxDynamicSharedMemorySize, SMEM_BYTES);

    zero_counters<<<1, 32>>>();
    {
        dim3 g(DH / 32, DM / 32, NE);          // (64, 64, 16)
        round_transpose_w<<<g, 256>>>(ew);
    }
    router_kernel<<<NT / 8, 256>>>(x, rw);

    dim3 grid(DH / BN, NT / BM, NE);           // (8, 64, 16), early-exit on cnt
    moe_gemm_kernel<<<grid, 256, SMEM_BYTES>>>();

    combine_kernel<<<(NT * DH / 4) / 256, 256>>>((float4*)out);
}

// round 10
// speedup vs baseline: 2.2508x; 1.5916x over previous
#include <cuda_runtime.h>
#include <cuda_fp16.h>
#include <cstdint>
#include <math.h>

#define NT 8192
#define DM 2048
#define DH 2048
#define NE 16

#define BM 128
#define BN 256
#define BK 64                   // 64 halves = 128 B rows (same geometry as R8)
#define KTILES (DM / BK)        // 32
#define NSTAGE 4

#define A_BYTES 16384           // 128 m-rows * 128 B
#define B_BYTES 32768           // 256 n-rows * 128 B
#define STAGE_BYTES (A_BYTES + B_BYTES)         // 48 KB
#define SMEM_BYTES (NSTAGE * STAGE_BYTES + 1024)

#define SWZ(o) ((unsigned)(o) ^ ((((unsigned)(o)) >> 3) & 0x70))

// ---------------- device scratch (allocation-free) ----------------
__device__ int    g_count[NE];
__device__ int    g_list[NE][NT];                   // token*2 + slot
__device__ float  g_gate[NE][NT];
__device__ float  g_scratch[(size_t)NT * 2 * DH];   // 128 MB combine scratch
__device__ __half g_xh[(size_t)NT * DM];            // 32 MB  fp16 x
__device__ __half g_wh[(size_t)NE * DH * DM];       // 128 MB fp16 W, transposed [e][n][k]

// ---------------- helpers ----------------
__device__ __forceinline__ uint32_t smem_u32(const void* p) {
    return (uint32_t)__cvta_generic_to_shared(p);
}
__device__ __forceinline__ void mma_f16(float& c0, float& c1, float& c2, float& c3,
                                        unsigned a0, unsigned a1, unsigned a2, unsigned a3,
                                        unsigned b0, unsigned b1) {
    asm volatile(
        "mma.sync.aligned.m16n8k16.row.col.f32.f16.f16.f32 "
        "{%0,%1,%2,%3}, {%4,%5,%6,%7}, {%8,%9}, {%0,%1,%2,%3};"
        : "+f"(c0), "+f"(c1), "+f"(c2), "+f"(c3)
        : "r"(a0), "r"(a1), "r"(a2), "r"(a3), "r"(b0), "r"(b1));
}
#define LDSM_X4(r0, r1, r2, r3, addr)                                        \
    asm volatile("ldmatrix.sync.aligned.m8n8.x4.shared.b16 {%0,%1,%2,%3}, [%4];" \
        : "=r"(r0), "=r"(r1), "=r"(r2), "=r"(r3) : "r"(addr))

#define CP_ASYNC16(dst, src) \
    asm volatile("cp.async.cg.shared.global [%0], [%1], 16;" :: "r"(dst), "l"(src))
#define CP_COMMIT()  asm volatile("cp.async.commit_group;" ::)
#define CP_WAIT(n)   asm volatile("cp.async.wait_group %0;" :: "n"(n))

// ---------------------------------------------------------------------------
__global__ void zero_counters() {
    if (threadIdx.x < NE) g_count[threadIdx.x] = 0;
}

// ---------------------------------------------------------------------------
// Convert W to fp16 AND transpose to [e][n][k] (k contiguous) for ldmatrix
// ---------------------------------------------------------------------------
__global__ void round_transpose_w(const float* __restrict__ w) {
    __shared__ float tile[32][33];
    const int e  = blockIdx.z;
    const int n0 = blockIdx.x * 32;
    const int k0 = blockIdx.y * 32;
    const int tx = threadIdx.x & 31;
    const int ty = threadIdx.x >> 5;   // 0..7

    const float* src = w + ((size_t)e * DM + k0) * DH + n0;
#pragma unroll
    for (int j = 0; j < 4; j++)
        tile[ty + j * 8][tx] = src[(size_t)(ty + j * 8) * DH + tx];
    __syncthreads();
    __half* dst = g_wh + ((size_t)e * DH + n0) * DM + k0;
#pragma unroll
    for (int j = 0; j < 4; j++)
        dst[(size_t)(ty + j * 8) * DM + tx] = __float2half_rn(tile[tx][ty + j * 8]);
}

// ---------------------------------------------------------------------------
// Router: warp per token; also writes fp16 x copy
// ---------------------------------------------------------------------------
__global__ void router_kernel(const float* __restrict__ x,
                              const float* __restrict__ rw) {
    int token = (blockIdx.x * blockDim.x + threadIdx.x) >> 5;
    int lane  = threadIdx.x & 31;
    if (token >= NT) return;

    const float* xr = x + (size_t)token * DM;
    __half* xo = g_xh + (size_t)token * DM;
    float acc[NE];
#pragma unroll
    for (int e = 0; e < NE; e++) acc[e] = 0.f;

    for (int i = lane; i < DM; i += 32) {
        float xv = xr[i];
        xo[i] = __float2half_rn(xv);
#pragma unroll
        for (int e = 0; e < NE; e++)
            acc[e] = fmaf(xv, rw[e * DM + i], acc[e]);
    }
#pragma unroll
    for (int off = 16; off > 0; off >>= 1) {
#pragma unroll
        for (int e = 0; e < NE; e++)
            acc[e] += __shfl_xor_sync(0xFFFFFFFFu, acc[e], off);
    }

    if (lane == 0) {
        int i1 = 0; float v1 = acc[0];
#pragma unroll
        for (int e = 1; e < NE; e++)
            if (acc[e] > v1) { v1 = acc[e]; i1 = e; }
        int i2 = -1; float v2 = -3.402823466e38f;
#pragma unroll
        for (int e = 0; e < NE; e++)
            if (e != i1 && acc[e] > v2) { v2 = acc[e]; i2 = e; }

        float t  = expf(v2 - v1);
        float g1 = 1.f / (1.f + t);
        float g2 = t * g1;

        int p1 = atomicAdd(&g_count[i1], 1);
        g_list[i1][p1] = token * 2 + 0; g_gate[i1][p1] = g1;
        int p2 = atomicAdd(&g_count[i2], 1);
        g_list[i2][p2] = token * 2 + 1; g_gate[i2][p2] = g2;
    }
}

// ---------------------------------------------------------------------------
// Gathered per-expert GEMM: CTA 128x256, warp tile 64x64, fp16 m16n8k16,
// 4-stage cp.async (BK=64), register fragment double-buffering. 8 warps.
// ---------------------------------------------------------------------------
__global__ void __launch_bounds__(256, 1)
moe_gemm_kernel() {
    extern __shared__ char dyn[];
    const uint32_t sbase = (smem_u32(dyn) + 1023u) & ~1023u;

    const int e   = blockIdx.z;
    const int cnt = g_count[e];
    const int m0  = blockIdx.y * BM;
    if (m0 >= cnt) return;
    const int n0  = blockIdx.x * BN;

    const int tid  = threadIdx.x;
    const int lane = tid & 31;
    const int wid  = tid >> 5;
    const int wm   = wid & 1;     // 2 warp-rows (64 M each)
    const int wn   = wid >> 1;    // 4 warp-cols (64 N each)
    const int grp  = lane >> 2;
    const int tg   = lane & 3;

    // ---- cp.async setup: 4 A-chunks + 8 B-chunks (16B) per thread ----
    const int rr  = tid >> 3;             // 0..31 (row within 32-row group)
    const int cc8 = tid & 7;              // 16B chunk within 128B row
    const uint32_t off0 = SWZ(rr * 128 + cc8 * 16);
    const __half* aSrc[4];
#pragma unroll
    for (int i = 0; i < 4; i++) {
        int gm = m0 + rr + 32 * i; if (gm >= cnt) gm = cnt - 1;
        int tok = g_list[e][gm] >> 1;
        aSrc[i] = g_xh + (size_t)tok * DM + cc8 * 8;
    }
    const __half* bSrc = g_wh + ((size_t)e * DH + n0 + rr) * DM + cc8 * 8;

#define LOAD_STAGE(s, kt)                                                    \
    do {                                                                     \
        uint32_t _b = sbase + (uint32_t)(s) * STAGE_BYTES;                   \
        _Pragma("unroll")                                                    \
        for (int i = 0; i < 4; i++)                                          \
            CP_ASYNC16(_b + off0 + i * 4096u, aSrc[i] + (kt) * BK);          \
        _Pragma("unroll")                                                    \
        for (int i = 0; i < 8; i++)                                          \
            CP_ASYNC16(_b + A_BYTES + off0 + i * 4096u,                      \
                       bSrc + (size_t)i * 32 * DM + (kt) * BK);              \
        CP_COMMIT();                                                         \
    } while (0)

    LOAD_STAGE(0, 0);
    LOAD_STAGE(1, 1);
    LOAD_STAGE(2, 2);

    // ---- ldmatrix per-thread geometry (same 128B-row/8-chunk map as R8) ----
    const uint32_t key = lane & 7;
    const uint32_t aRB = (uint32_t)(wm * 64 + ((lane >> 3) & 1) * 8 + (lane & 7)) * 128;
    const uint32_t aCH = (lane >> 4) & 1;
    const uint32_t bRB = (uint32_t)(wn * 64 + ((lane >> 4) & 1) * 8 + (lane & 7)) * 128;
    const uint32_t bCH = (lane >> 3) & 1;

    float c[4][8][4];
#pragma unroll
    for (int mb = 0; mb < 4; mb++)
#pragma unroll
        for (int nb = 0; nb < 8; nb++)
#pragma unroll
            for (int j = 0; j < 4; j++) c[mb][nb][j] = 0.f;

    unsigned af[2][4][4];   // [buf][mb][frag]  (m16k16 -> 4 regs)
    unsigned bf[2][4][4];   // [buf][nb2][mat]  (n16k16 -> 4 regs = 2 n8 frags)

#define LOAD_FRAGS(buf, sA, sB, ks)                                          \
    do {                                                                     \
        const uint32_t _ca = (((ks) * 2 + aCH) ^ key) << 4;                  \
        const uint32_t _cb = (((ks) * 2 + bCH) ^ key) << 4;                  \
        _Pragma("unroll")                                                    \
        for (int mb = 0; mb < 4; mb++)                                       \
            LDSM_X4(af[buf][mb][0], af[buf][mb][1], af[buf][mb][2],          \
                    af[buf][mb][3], (sA) + aRB + mb * 2048u + _ca);          \
        _Pragma("unroll")                                                    \
        for (int nb2 = 0; nb2 < 4; nb2++)                                    \
            LDSM_X4(bf[buf][nb2][0], bf[buf][nb2][1], bf[buf][nb2][2],       \
                    bf[buf][nb2][3], (sB) + bRB + nb2 * 2048u + _cb);        \
    } while (0)

#define MMA_FRAGS(buf)                                                       \
    do {                                                                     \
        _Pragma("unroll")                                                    \
        for (int mb = 0; mb < 4; mb++)                                       \
            _Pragma("unroll")                                                \
            for (int nb = 0; nb < 8; nb++) {                                 \
                const unsigned b0 = bf[buf][nb >> 1][(nb & 1) * 2];          \
                const unsigned b1 = bf[buf][nb >> 1][(nb & 1) * 2 + 1];      \
                mma_f16(c[mb][nb][0], c[mb][nb][1], c[mb][nb][2],            \
                        c[mb][nb][3], af[buf][mb][0], af[buf][mb][1],        \
                        af[buf][mb][2], af[buf][mb][3], b0, b1);             \
            }                                                                \
    } while (0)

    for (int kt = 0; kt < KTILES; kt++) {
        if (kt < KTILES - 2)       CP_WAIT(2);
        else if (kt == KTILES - 2) CP_WAIT(1);
        else                       CP_WAIT(0);
        __syncthreads();

        if (kt + 3 < KTILES) LOAD_STAGE((kt + 3) & 3, kt + 3);

        const uint32_t sA = sbase + (uint32_t)(kt & 3) * STAGE_BYTES;
        const uint32_t sB = sA + A_BYTES;

        LOAD_FRAGS(0, sA, sB, 0);
#pragma unroll
        for (int ks = 0; ks < 4; ks++) {          // 4 x k16 in BK=64
            if (ks < 3) LOAD_FRAGS((ks + 1) & 1, sA, sB, ks + 1);
            MMA_FRAGS(ks & 1);
        }
    }
#undef LOAD_STAGE
#undef LOAD_FRAGS
#undef MMA_FRAGS

    // ---- epilogue: gate-scale, STG.64 into disjoint (token,slot) scratch rows ----
#pragma unroll
    for (int mb = 0; mb < 4; mb++) {
#pragma unroll
        for (int half = 0; half < 2; half++) {
            int gm = m0 + wm * 64 + mb * 16 + grp + half * 8;
            if (gm >= cnt) continue;
            int   sl = g_list[e][gm];
            float gt = g_gate[e][gm];
            float* orow = g_scratch + (size_t)sl * DH + n0 + wn * 64;
#pragma unroll
            for (int nb = 0; nb < 8; nb++) {
                int col = nb * 8 + 2 * tg;
                float2 v = make_float2(gt * c[mb][nb][half * 2 + 0],
                                       gt * c[mb][nb][half * 2 + 1]);
                *reinterpret_cast<float2*>(orow + col) = v;
            }
        }
    }
}

// ---------------------------------------------------------------------------
// Combine: out[t] = scratch[2t] + scratch[2t+1]
// ---------------------------------------------------------------------------
__global__ void combine_kernel(float4* __restrict__ out) {
    const int C = DH / 4;
    int i = blockIdx.x * blockDim.x + threadIdx.x;
    int t = i / C, col = i - t * C;
    const float4* s = reinterpret_cast<const float4*>(g_scratch);
    float4 a = s[(size_t)(2 * t) * C + col];
    float4 b = s[(size_t)(2 * t + 1) * C + col];
    out[i] = make_float4(a.x + b.x, a.y + b.y, a.z + b.z, a.w + b.w);
}

// ---------------------------------------------------------------------------
extern "C" void kernel_launch(void* const* d_in, const int* in_sizes, int n_in,
                              void* d_out, int out_size) {
    const float* x  = (const float*)d_in[0];   // [NT, DM]
    const float* rw = (const float*)d_in[1];   // [NE, DM]
    const float* ew = (const float*)d_in[2];   // [NE, DM, DH]
    float* out = (float*)d_out;                // [NT, DH]

    cudaFuncSetAttribute(moe_gemm_kernel,
                         cudaFuncAttributeMaxDynamicSharedMemorySize, SMEM_BYTES);

    zero_counters<<<1, 32>>>();
    {
        dim3 g(DH / 32, DM / 32, NE);          // (64, 64, 16)
        round_transpose_w<<<g, 256>>>(ew);
    }
    router_kernel<<<NT / 8, 256>>>(x, rw);

    dim3 grid(DH / BN, NT / BM, NE);           // (8, 64, 16), early-exit on cnt
    moe_gemm_kernel<<<grid, 256, SMEM_BYTES>>>();

    combine_kernel<<<(NT * DH / 4) / 256, 256>>>((float4*)out);
}

// round 12
// speedup vs baseline: 2.3050x; 1.0241x over previous
#include <cuda_runtime.h>
#include <cuda_fp16.h>
#include <cstdint>
#include <math.h>

#define NT 8192
#define DM 2048
#define DH 2048
#define NE 16

#define BM 128
#define BN 256
#define BK 64                   // 64 halves deep
#define KTILES (DM / BK)        // 32
#define NSTAGE 4

#define A_BYTES 16384           // 128 m-rows * 128 B (k-major, swizzled)
#define B_BYTES 32768           // 64 k-rows * 512 B (n-major, swizzled)
#define STAGE_BYTES (A_BYTES + B_BYTES)         // 48 KB
#define SMEM_BYTES (NSTAGE * STAGE_BYTES + 1024)

#define SWZ(o) ((unsigned)(o) ^ ((((unsigned)(o)) >> 3) & 0x70))

// ---------------- device scratch (allocation-free) ----------------
__device__ int    g_count[NE];
__device__ int    g_list[NE][NT];                   // token*2 + slot
__device__ float  g_gate[NE][NT];
__device__ float  g_scratch[(size_t)NT * 2 * DH];   // 128 MB combine scratch
__device__ __half g_xh[(size_t)NT * DM];            // 32 MB  fp16 x
__device__ __half g_wh[(size_t)NE * DM * DH];       // 128 MB fp16 W, ORIGINAL [e][k][n] layout

// ---------------- helpers ----------------
__device__ __forceinline__ uint32_t smem_u32(const void* p) {
    return (uint32_t)__cvta_generic_to_shared(p);
}
__device__ __forceinline__ unsigned h2_bits(__half2 h) {
    __half2_raw r = *reinterpret_cast<__half2_raw*>(&h);
    return ((unsigned)r.y << 16) | (unsigned)r.x;
}
__device__ __forceinline__ void mma_f16(float& c0, float& c1, float& c2, float& c3,
                                        unsigned a0, unsigned a1, unsigned a2, unsigned a3,
                                        unsigned b0, unsigned b1) {
    asm volatile(
        "mma.sync.aligned.m16n8k16.row.col.f32.f16.f16.f32 "
        "{%0,%1,%2,%3}, {%4,%5,%6,%7}, {%8,%9}, {%0,%1,%2,%3};"
        : "+f"(c0), "+f"(c1), "+f"(c2), "+f"(c3)
        : "r"(a0), "r"(a1), "r"(a2), "r"(a3), "r"(b0), "r"(b1));
}
#define LDSM_X4(r0, r1, r2, r3, addr)                                        \
    asm volatile("ldmatrix.sync.aligned.m8n8.x4.shared.b16 {%0,%1,%2,%3}, [%4];" \
        : "=r"(r0), "=r"(r1), "=r"(r2), "=r"(r3) : "r"(addr))
#define LDSM_X4_T(r0, r1, r2, r3, addr)                                      \
    asm volatile("ldmatrix.sync.aligned.m8n8.x4.trans.shared.b16 {%0,%1,%2,%3}, [%4];" \
        : "=r"(r0), "=r"(r1), "=r"(r2), "=r"(r3) : "r"(addr))

#define CP_ASYNC16(dst, src) \
    asm volatile("cp.async.cg.shared.global [%0], [%1], 16;" :: "r"(dst), "l"(src))
#define CP_COMMIT()  asm volatile("cp.async.commit_group;" ::)
#define CP_WAIT(n)   asm volatile("cp.async.wait_group %0;" :: "n"(n))

// ---------------------------------------------------------------------------
__global__ void zero_counters() {
    if (threadIdx.x < NE) g_count[threadIdx.x] = 0;
}

// ---------------------------------------------------------------------------
// Pure streaming convert: W fp32 -> fp16, layout preserved [e][k][n]
// ---------------------------------------------------------------------------
__global__ void convert_w(const float4* __restrict__ w) {
    size_t i = (size_t)blockIdx.x * blockDim.x + threadIdx.x;   // < NE*DM*DH/8
    float4 v0 = w[2 * i];
    float4 v1 = w[2 * i + 1];
    uint4 p;
    p.x = h2_bits(__float22half2_rn(make_float2(v0.x, v0.y)));
    p.y = h2_bits(__float22half2_rn(make_float2(v0.z, v0.w)));
    p.z = h2_bits(__float22half2_rn(make_float2(v1.x, v1.y)));
    p.w = h2_bits(__float22half2_rn(make_float2(v1.z, v1.w)));
    reinterpret_cast<uint4*>(g_wh)[i] = p;
}

// ---------------------------------------------------------------------------
// Router: warp per token; also writes fp16 x copy
// ---------------------------------------------------------------------------
__global__ void router_kernel(const float* __restrict__ x,
                              const float* __restrict__ rw) {
    int token = (blockIdx.x * blockDim.x + threadIdx.x) >> 5;
    int lane  = threadIdx.x & 31;
    if (token >= NT) return;

    const float* xr = x + (size_t)token * DM;
    __half* xo = g_xh + (size_t)token * DM;
    float acc[NE];
#pragma unroll
    for (int e = 0; e < NE; e++) acc[e] = 0.f;

    for (int i = lane; i < DM; i += 32) {
        float xv = xr[i];
        xo[i] = __float2half_rn(xv);
#pragma unroll
        for (int e = 0; e < NE; e++)
            acc[e] = fmaf(xv, rw[e * DM + i], acc[e]);
    }
#pragma unroll
    for (int off = 16; off > 0; off >>= 1) {
#pragma unroll
        for (int e = 0; e < NE; e++)
            acc[e] += __shfl_xor_sync(0xFFFFFFFFu, acc[e], off);
    }

    if (lane == 0) {
        int i1 = 0; float v1 = acc[0];
#pragma unroll
        for (int e = 1; e < NE; e++)
            if (acc[e] > v1) { v1 = acc[e]; i1 = e; }
        int i2 = -1; float v2 = -3.402823466e38f;
#pragma unroll
        for (int e = 0; e < NE; e++)
            if (e != i1 && acc[e] > v2) { v2 = acc[e]; i2 = e; }

        float t  = expf(v2 - v1);
        float g1 = 1.f / (1.f + t);
        float g2 = t * g1;

        int p1 = atomicAdd(&g_count[i1], 1);
        g_list[i1][p1] = token * 2 + 0; g_gate[i1][p1] = g1;
        int p2 = atomicAdd(&g_count[i2], 1);
        g_list[i2][p2] = token * 2 + 1; g_gate[i2][p2] = g2;
    }
}

// ---------------------------------------------------------------------------
// Gathered per-expert GEMM: CTA 128x256, warp tile 64x64, fp16 m16n8k16.
// A: [m][k] 128B rows (SWZ). B: [k][n] 512B rows, swizzle o^((k&7)<<4),
// consumed via ldmatrix.trans. 4-stage cp.async, fragment double-buffering.
// ---------------------------------------------------------------------------
__global__ void __launch_bounds__(256, 1)
moe_gemm_kernel() {
    extern __shared__ char dyn[];
    const uint32_t sbase = (smem_u32(dyn) + 1023u) & ~1023u;

    const int e   = blockIdx.z;
    const int cnt = g_count[e];
    const int m0  = blockIdx.y * BM;
    if (m0 >= cnt) return;
    const int n0  = blockIdx.x * BN;

    const int tid  = threadIdx.x;
    const int lane = tid & 31;
    const int wid  = tid >> 5;
    const int wm   = wid & 1;     // 2 warp-rows (64 M each)
    const int wn   = wid >> 1;    // 4 warp-cols (64 N each)
    const int grp  = lane >> 2;
    const int tg   = lane & 3;

    // ---- A cp.async: 4 chunks/thread, [m][k] 128B rows, SWZ (unchanged) ----
    const int rr  = tid >> 3;             // 0..31
    const int cc8 = tid & 7;              // 16B chunk in 128B row
    const uint32_t aOff0 = SWZ(rr * 128 + cc8 * 16);
    const __half* aSrc[4];
#pragma unroll
    for (int i = 0; i < 4; i++) {
        int gm = m0 + rr + 32 * i; if (gm >= cnt) gm = cnt - 1;
        int tok = g_list[e][gm] >> 1;
        aSrc[i] = g_xh + (size_t)tok * DM + cc8 * 8;
    }

    // ---- B cp.async: 8 chunks/thread, [k][n] 512B rows ----
    // thread base: k-row = tid>>3 (+32 per i>=4), chunk ci = tid&7 (+8 per i&3)
    // smem: o = k*512 + ci*16, phys = o ^ ((k&7)<<4); (k&7) const per thread.
    const __half* bSrc0 = g_wh + ((size_t)e * DM + (tid >> 3)) * DH + n0 + (tid & 7) * 8;
    const uint32_t bOff0 = (uint32_t)((tid >> 3) * 512 + (tid & 7) * 16)
                           ^ ((((uint32_t)tid >> 3) & 7) << 4);

#define LOAD_STAGE(s, kt)                                                    \
    do {                                                                     \
        uint32_t _b = sbase + (uint32_t)(s) * STAGE_BYTES;                   \
        _Pragma("unroll")                                                    \
        for (int i = 0; i < 4; i++)                                          \
            CP_ASYNC16(_b + aOff0 + i * 4096u, aSrc[i] + (kt) * BK);         \
        _Pragma("unroll")                                                    \
        for (int i = 0; i < 8; i++)                                          \
            CP_ASYNC16(_b + A_BYTES + bOff0 + (i >> 2) * 16384u + (i & 3) * 128u, \
                       bSrc0 + ((size_t)(kt) * BK + (i >> 2) * 32) * DH + (i & 3) * 64); \
        CP_COMMIT();                                                         \
    } while (0)

    LOAD_STAGE(0, 0);
    LOAD_STAGE(1, 1);
    LOAD_STAGE(2, 2);

    // ---- A ldmatrix geometry (unchanged from R10) ----
    const uint32_t key = lane & 7;
    const uint32_t aRB = (uint32_t)(wm * 64 + ((lane >> 3) & 1) * 8 + (lane & 7)) * 128;
    const uint32_t aCH = (lane >> 4) & 1;

    // ---- B ldmatrix.trans geometry ----
    // mat = lane>>3: mat0=(k0-7,n0-7) mat1=(k8-15,n0-7) mat2=(k0-7,n8-15) mat3=(k8-15,n8-15)
    const uint32_t mat  = lane >> 3;
    const uint32_t k_r  = (mat & 1) * 8 + (lane & 7);          // 0..15
    const uint32_t n_b  = (uint32_t)(wn * 64) + (mat >> 1) * 8;
    const uint32_t bBase = k_r * 512 + n_b * 2;                 // pre-XOR logical base
    const uint32_t bXOR  = (k_r & 7) << 4;

    float c[4][8][4];
#pragma unroll
    for (int mb = 0; mb < 4; mb++)
#pragma unroll
        for (int nb = 0; nb < 8; nb++)
#pragma unroll
            for (int j = 0; j < 4; j++) c[mb][nb][j] = 0.f;

    unsigned af[2][4][4];   // [buf][mb][frag]
    unsigned bf[2][4][4];   // [buf][nb2][frag]  (n16k16 via trans LDSM)

#define LOAD_FRAGS(buf, sA, sB, ks)                                          \
    do {                                                                     \
        const uint32_t _ca = (((ks) * 2 + aCH) ^ key) << 4;                  \
        _Pragma("unroll")                                                    \
        for (int mb = 0; mb < 4; mb++)                                       \
            LDSM_X4(af[buf][mb][0], af[buf][mb][1], af[buf][mb][2],          \
                    af[buf][mb][3], (sA) + aRB + mb * 2048u + _ca);          \
        _Pragma("unroll")                                                    \
        for (int nb2 = 0; nb2 < 4; nb2++)                                    \
            LDSM_X4_T(bf[buf][nb2][0], bf[buf][nb2][1], bf[buf][nb2][2],     \
                      bf[buf][nb2][3],                                       \
                      (sB) + ((bBase + (ks) * 8192u + nb2 * 32u) ^ bXOR));   \
    } while (0)

#define MMA_FRAGS(buf)                                                       \
    do {                                                                     \
        _Pragma("unroll")                                                    \
        for (int mb = 0; mb < 4; mb++)                                       \
            _Pragma("unroll")                                                \
            for (int nb = 0; nb < 8; nb++) {                                 \
                const unsigned b0 = bf[buf][nb >> 1][(nb & 1) * 2];          \
                const unsigned b1 = bf[buf][nb >> 1][(nb & 1) * 2 + 1];      \
                mma_f16(c[mb][nb][0], c[mb][nb][1], c[mb][nb][2],            \
                        c[mb][nb][3], af[buf][mb][0], af[buf][mb][1],        \
                        af[buf][mb][2], af[buf][mb][3], b0, b1);             \
            }                                                                \
    } while (0)

    for (int kt = 0; kt < KTILES; kt++) {
        if (kt < KTILES - 2)       CP_WAIT(2);
        else if (kt == KTILES - 2) CP_WAIT(1);
        else                       CP_WAIT(0);
        __syncthreads();

        if (kt + 3 < KTILES) LOAD_STAGE((kt + 3) & 3, kt + 3);

        const uint32_t sA = sbase + (uint32_t)(kt & 3) * STAGE_BYTES;
        const uint32_t sB = sA + A_BYTES;

        LOAD_FRAGS(0, sA, sB, 0);
#pragma unroll
        for (int ks = 0; ks < 4; ks++) {          // 4 x k16 in BK=64
            if (ks < 3) LOAD_FRAGS((ks + 1) & 1, sA, sB, ks + 1);
            MMA_FRAGS(ks & 1);
        }
    }
#undef LOAD_STAGE
#undef LOAD_FRAGS
#undef MMA_FRAGS

    // ---- epilogue: gate-scale, STG.64 into disjoint (token,slot) scratch rows ----
#pragma unroll
    for (int mb = 0; mb < 4; mb++) {
#pragma unroll
        for (int half = 0; half < 2; half++) {
            int gm = m0 + wm * 64 + mb * 16 + grp + half * 8;
            if (gm >= cnt) continue;
            int   sl = g_list[e][gm];
            float gt = g_gate[e][gm];
            float* orow = g_scratch + (size_t)sl * DH + n0 + wn * 64;
#pragma unroll
            for (int nb = 0; nb < 8; nb++) {
                int col = nb * 8 + 2 * tg;
                float2 v = make_float2(gt * c[mb][nb][half * 2 + 0],
                                       gt * c[mb][nb][half * 2 + 1]);
                *reinterpret_cast<float2*>(orow + col) = v;
            }
        }
    }
}

// ---------------------------------------------------------------------------
// Combine: out[t] = scratch[2t] + scratch[2t+1]
// ---------------------------------------------------------------------------
__global__ void combine_kernel(float4* __restrict__ out) {
    const int C = DH / 4;
    int i = blockIdx.x * blockDim.x + threadIdx.x;
    int t = i / C, col = i - t * C;
    const float4* s = reinterpret_cast<const float4*>(g_scratch);
    float4 a = s[(size_t)(2 * t) * C + col];
    float4 b = s[(size_t)(2 * t + 1) * C + col];
    out[i] = make_float4(a.x + b.x, a.y + b.y, a.z + b.z, a.w + b.w);
}

// ---------------------------------------------------------------------------
extern "C" void kernel_launch(void* const* d_in, const int* in_sizes, int n_in,
                              void* d_out, int out_size) {
    const float* x  = (const float*)d_in[0];   // [NT, DM]
    const float* rw = (const float*)d_in[1];   // [NE, DM]
    const float* ew = (const float*)d_in[2];   // [NE, DM, DH]
    float* out = (float*)d_out;                // [NT, DH]

    cudaFuncSetAttribute(moe_gemm_kernel,
                         cudaFuncAttributeMaxDynamicSharedMemorySize, SMEM_BYTES);

    zero_counters<<<1, 32>>>();
    convert_w<<<(NE * DM * DH / 8) / 256, 256>>>((const float4*)ew);
    router_kernel<<<NT / 8, 256>>>(x, rw);

    dim3 grid(DH / BN, NT / BM, NE);           // (8, 64, 16), early-exit on cnt
    moe_gemm_kernel<<<grid, 256, SMEM_BYTES>>>();

    combine_kernel<<<(NT * DH / 4) / 256, 256>>>((float4*)out);
}

// round 15
// speedup vs baseline: 2.3805x; 1.0328x over previous
#include <cuda_runtime.h>
#include <cuda_fp16.h>
#include <cstdint>
#include <math.h>

#define NT 8192
#define DM 2048
#define DH 2048
#define NE 16

#define BM 128
#define BN 256
#define BK 64                   // 64 halves deep
#define KTILES (DM / BK)        // 32
#define NSTAGE 4
#define THREADS 512

#define A_BYTES 16384           // 128 m-rows * 128 B (k-major, swizzled)
#define B_BYTES 32768           // 64 k-rows * 512 B (n-major, swizzled)
#define STAGE_BYTES (A_BYTES + B_BYTES)         // 48 KB
#define SMEM_BYTES (NSTAGE * STAGE_BYTES + 1024)

#define SWZ(o) ((unsigned)(o) ^ ((((unsigned)(o)) >> 3) & 0x70))

// ---------------- device scratch (allocation-free) ----------------
__device__ int    g_count[NE];
__device__ int    g_list[NE][NT];                   // token*2 + slot
__device__ float  g_gate[NE][NT];
__device__ float  g_scratch[(size_t)NT * 2 * DH];   // 128 MB combine scratch
__device__ __half g_xh[(size_t)NT * DM];            // 32 MB  fp16 x
__device__ __half g_wh[(size_t)NE * DM * DH];       // 128 MB fp16 W, original [e][k][n]

// ---------------- helpers ----------------
__device__ __forceinline__ uint32_t smem_u32(const void* p) {
    return (uint32_t)__cvta_generic_to_shared(p);
}
__device__ __forceinline__ unsigned h2_bits(__half2 h) {
    __half2_raw r = *reinterpret_cast<__half2_raw*>(&h);
    return ((unsigned)r.y << 16) | (unsigned)r.x;
}
__device__ __forceinline__ void mma_f16(float& c0, float& c1, float& c2, float& c3,
                                        unsigned a0, unsigned a1, unsigned a2, unsigned a3,
                                        unsigned b0, unsigned b1) {
    asm volatile(
        "mma.sync.aligned.m16n8k16.row.col.f32.f16.f16.f32 "
        "{%0,%1,%2,%3}, {%4,%5,%6,%7}, {%8,%9}, {%0,%1,%2,%3};"
        : "+f"(c0), "+f"(c1), "+f"(c2), "+f"(c3)
        : "r"(a0), "r"(a1), "r"(a2), "r"(a3), "r"(b0), "r"(b1));
}
#define LDSM_X4(r0, r1, r2, r3, addr)                                        \
    asm volatile("ldmatrix.sync.aligned.m8n8.x4.shared.b16 {%0,%1,%2,%3}, [%4];" \
        : "=r"(r0), "=r"(r1), "=r"(r2), "=r"(r3) : "r"(addr))
#define LDSM_X4_T(r0, r1, r2, r3, addr)                                      \
    asm volatile("ldmatrix.sync.aligned.m8n8.x4.trans.shared.b16 {%0,%1,%2,%3}, [%4];" \
        : "=r"(r0), "=r"(r1), "=r"(r2), "=r"(r3) : "r"(addr))

#define CP_ASYNC16(dst, src) \
    asm volatile("cp.async.cg.shared.global [%0], [%1], 16;" :: "r"(dst), "l"(src))
#define CP_COMMIT()  asm volatile("cp.async.commit_group;" ::)
#define CP_WAIT(n)   asm volatile("cp.async.wait_group %0;" :: "n"(n))

// ---------------------------------------------------------------------------
// Streaming convert W fp32->fp16 (layout preserved) + counter zeroing (fused)
// ---------------------------------------------------------------------------
__global__ void convert_w(const float4* __restrict__ w) {
    if (blockIdx.x == 0 && threadIdx.x < NE) g_count[threadIdx.x] = 0;
    size_t i = (size_t)blockIdx.x * blockDim.x + threadIdx.x;   // < NE*DM*DH/8
    float4 v0 = w[2 * i];
    float4 v1 = w[2 * i + 1];
    uint4 p;
    p.x = h2_bits(__float22half2_rn(make_float2(v0.x, v0.y)));
    p.y = h2_bits(__float22half2_rn(make_float2(v0.z, v0.w)));
    p.z = h2_bits(__float22half2_rn(make_float2(v1.x, v1.y)));
    p.w = h2_bits(__float22half2_rn(make_float2(v1.z, v1.w)));
    reinterpret_cast<uint4*>(g_wh)[i] = p;
}

// ---------------------------------------------------------------------------
// Router: warp per token; also writes fp16 x copy
// ---------------------------------------------------------------------------
__global__ void router_kernel(const float* __restrict__ x,
                              const float* __restrict__ rw) {
    int token = (blockIdx.x * blockDim.x + threadIdx.x) >> 5;
    int lane  = threadIdx.x & 31;
    if (token >= NT) return;

    const float* xr = x + (size_t)token * DM;
    __half* xo = g_xh + (size_t)token * DM;
    float acc[NE];
#pragma unroll
    for (int e = 0; e < NE; e++) acc[e] = 0.f;

    for (int i = lane; i < DM; i += 32) {
        float xv = xr[i];
        xo[i] = __float2half_rn(xv);
#pragma unroll
        for (int e = 0; e < NE; e++)
            acc[e] = fmaf(xv, rw[e * DM + i], acc[e]);
    }
#pragma unroll
    for (int off = 16; off > 0; off >>= 1) {
#pragma unroll
        for (int e = 0; e < NE; e++)
            acc[e] += __shfl_xor_sync(0xFFFFFFFFu, acc[e], off);
    }

    if (lane == 0) {
        int i1 = 0; float v1 = acc[0];
#pragma unroll
        for (int e = 1; e < NE; e++)
            if (acc[e] > v1) { v1 = acc[e]; i1 = e; }
        int i2 = -1; float v2 = -3.402823466e38f;
#pragma unroll
        for (int e = 0; e < NE; e++)
            if (e != i1 && acc[e] > v2) { v2 = acc[e]; i2 = e; }

        float t  = expf(v2 - v1);
        float g1 = 1.f / (1.f + t);
        float g2 = t * g1;

        int p1 = atomicAdd(&g_count[i1], 1);
        g_list[i1][p1] = token * 2 + 0; g_gate[i1][p1] = g1;
        int p2 = atomicAdd(&g_count[i2], 1);
        g_list[i2][p2] = token * 2 + 1; g_gate[i2][p2] = g2;
    }
}

// ---------------------------------------------------------------------------
// Gathered per-expert GEMM: CTA 128x256, 16 warps, warp tile 32x64,
// fp16 m16n8k16, 4-stage cp.async, fragment double-buffering.
// 4 warps/SMSP for latency hiding across barriers.
// ---------------------------------------------------------------------------
__global__ void __launch_bounds__(THREADS, 1)
moe_gemm_kernel() {
    extern __shared__ char dyn[];
    const uint32_t sbase = (smem_u32(dyn) + 1023u) & ~1023u;

    const int e   = blockIdx.z;
    const int cnt = g_count[e];
    const int m0  = blockIdx.y * BM;
    if (m0 >= cnt) return;
    const int n0  = blockIdx.x * BN;

    const int tid  = threadIdx.x;
    const int lane = tid & 31;
    const int wid  = tid >> 5;
    const int wm   = wid & 3;     // 4 warp-rows (32 M each)
    const int wn   = wid >> 2;    // 4 warp-cols (64 N each)
    const int grp  = lane >> 2;
    const int tg   = lane & 3;

    // ---- A cp.async: 2 chunks/thread, [m][k] 128B rows, SWZ ----
    const int rrA  = tid >> 3;            // 0..63
    const int cc8  = tid & 7;             // 16B chunk in 128B row
    const __half* aSrc[2];
#pragma unroll
    for (int i = 0; i < 2; i++) {
        int gm = m0 + rrA + 64 * i; if (gm >= cnt) gm = cnt - 1;
        int tok = g_list[e][gm] >> 1;
        aSrc[i] = g_xh + (size_t)tok * DM + cc8 * 8;
    }
    const uint32_t aOff0 = SWZ(rrA * 128 + cc8 * 16);   // +64 rows = +8192B (SWZ-safe)

    // ---- B cp.async: 4 chunks/thread, [k][n] 512B rows ----
    // chunk v = tid + 512*i: k = (tid>>5) + 16*i, ci = tid&31
    // phys = (k*512 + ci*16) ^ ((k&7)<<4); (k&7) const across i.
    const int kB  = tid >> 5;             // 0..15
    const int ciB = tid & 31;
    const __half* bSrc0 = g_wh + ((size_t)e * DM + kB) * DH + n0 + ciB * 8;
    const uint32_t bOff0 = (uint32_t)(kB * 512 + ciB * 16) ^ (((uint32_t)kB & 7) << 4);

#define LOAD_STAGE(s, kt)                                                    \
    do {                                                                     \
        uint32_t _b = sbase + (uint32_t)(s) * STAGE_BYTES;                   \
        _Pragma("unroll")                                                    \
        for (int i = 0; i < 2; i++)                                          \
            CP_ASYNC16(_b + aOff0 + i * 8192u, aSrc[i] + (kt) * BK);         \
        _Pragma("unroll")                                                    \
        for (int i = 0; i < 4; i++)                                          \
            CP_ASYNC16(_b + A_BYTES + bOff0 + i * 8192u,                     \
                       bSrc0 + ((size_t)(kt) * BK + i * 16) * DH);           \
        CP_COMMIT();                                                         \
    } while (0)

    LOAD_STAGE(0, 0);
    LOAD_STAGE(1, 1);
    LOAD_STAGE(2, 2);

    // ---- A ldmatrix geometry (warp tile 32 M) ----
    const uint32_t key = lane & 7;
    const uint32_t aRB = (uint32_t)(wm * 32 + ((lane >> 3) & 1) * 8 + (lane & 7)) * 128;
    const uint32_t aCH = (lane >> 4) & 1;

    // ---- B ldmatrix.trans geometry (warp tile 64 N, unchanged from R12) ----
    const uint32_t mat  = lane >> 3;
    const uint32_t k_r  = (mat & 1) * 8 + (lane & 7);          // 0..15
    const uint32_t n_b  = (uint32_t)(wn * 64) + (mat >> 1) * 8;
    const uint32_t bBase = k_r * 512 + n_b * 2;
    const uint32_t bXOR  = (k_r & 7) << 4;

    float c[2][8][4];
#pragma unroll
    for (int mb = 0; mb < 2; mb++)
#pragma unroll
        for (int nb = 0; nb < 8; nb++)
#pragma unroll
            for (int j = 0; j < 4; j++) c[mb][nb][j] = 0.f;

    unsigned af[2][2][4];   // [buf][mb][frag]
    unsigned bf[2][4][4];   // [buf][nb2][frag]

#define LOAD_FRAGS(buf, sA, sB, ks)                                          \
    do {                                                                     \
        const uint32_t _ca = (((ks) * 2 + aCH) ^ key) << 4;                  \
        _Pragma("unroll")                                                    \
        for (int mb = 0; mb < 2; mb++)                                       \
            LDSM_X4(af[buf][mb][0], af[buf][mb][1], af[buf][mb][2],          \
                    af[buf][mb][3], (sA) + aRB + mb * 2048u + _ca);          \
        _Pragma("unroll")                                                    \
        for (int nb2 = 0; nb2 < 4; nb2++)                                    \
            LDSM_X4_T(bf[buf][nb2][0], bf[buf][nb2][1], bf[buf][nb2][2],     \
                      bf[buf][nb2][3],                                       \
                      (sB) + ((bBase + (ks) * 8192u + nb2 * 32u) ^ bXOR));   \
    } while (0)

#define MMA_FRAGS(buf)                                                       \
    do {                                                                     \
        _Pragma("unroll")                                                    \
        for (int mb = 0; mb < 2; mb++)                                       \
            _Pragma("unroll")                                                \
            for (int nb = 0; nb < 8; nb++) {                                 \
                const unsigned b0 = bf[buf][nb >> 1][(nb & 1) * 2];          \
                const unsigned b1 = bf[buf][nb >> 1][(nb & 1) * 2 + 1];     \
                mma_f16(c[mb][nb][0], c[mb][nb][1], c[mb][nb][2],            \
                        c[mb][nb][3], af[buf][mb][0], af[buf][mb][1],        \
                        af[buf][mb][2], af[buf][mb][3], b0, b1);             \
            }                                                                \
    } while (0)

    for (int kt = 0; kt < KTILES; kt++) {
        if (kt < KTILES - 2)       CP_WAIT(2);
        else if (kt == KTILES - 2) CP_WAIT(1);
        else                       CP_WAIT(0);
        __syncthreads();

        if (kt + 3 < KTILES) LOAD_STAGE((kt + 3) & 3, kt + 3);

        const uint32_t sA = sbase + (uint32_t)(kt & 3) * STAGE_BYTES;
        const uint32_t sB = sA + A_BYTES;

        LOAD_FRAGS(0, sA, sB, 0);
#pragma unroll
        for (int ks = 0; ks < 4; ks++) {          // 4 x k16 in BK=64
            if (ks < 3) LOAD_FRAGS((ks + 1) & 1, sA, sB, ks + 1);
            MMA_FRAGS(ks & 1);
        }
    }
#undef LOAD_STAGE
#undef LOAD_FRAGS
#undef MMA_FRAGS

    // ---- epilogue: gate-scale, STG.64 into disjoint (token,slot) scratch rows ----
#pragma unroll
    for (int mb = 0; mb < 2; mb++) {
#pragma unroll
        for (int half = 0; half < 2; half++) {
            int gm = m0 + wm * 32 + mb * 16 + grp + half * 8;
            if (gm >= cnt) continue;
            int   sl = g_list[e][gm];
            float gt = g_gate[e][gm];
            float* orow = g_scratch + (size_t)sl * DH + n0 + wn * 64;
#pragma unroll
            for (int nb = 0; nb < 8; nb++) {
                int col = nb * 8 + 2 * tg;
                float2 v = make_float2(gt * c[mb][nb][half * 2 + 0],
                                       gt * c[mb][nb][half * 2 + 1]);
                *reinterpret_cast<float2*>(orow + col) = v;
            }
        }
    }
}

// ---------------------------------------------------------------------------
// Combine: out[t] = scratch[2t] + scratch[2t+1]
// ---------------------------------------------------------------------------
__global__ void combine_kernel(float4* __restrict__ out) {
    const int C = DH / 4;
    int i = blockIdx.x * blockDim.x + threadIdx.x;
    int t = i / C, col = i - t * C;
    const float4* s = reinterpret_cast<const float4*>(g_scratch);
    float4 a = s[(size_t)(2 * t) * C + col];
    float4 b = s[(size_t)(2 * t + 1) * C + col];
    out[i] = make_float4(a.x + b.x, a.y + b.y, a.z + b.z, a.w + b.w);
}

// ---------------------------------------------------------------------------
extern "C" void kernel_launch(void* const* d_in, const int* in_sizes, int n_in,
                              void* d_out, int out_size) {
    const float* x  = (const float*)d_in[0];   // [NT, DM]
    const float* rw = (const float*)d_in[1];   // [NE, DM]
    const float* ew = (const float*)d_in[2];   // [NE, DM, DH]
    float* out = (float*)d_out;                // [NT, DH]

    cudaFuncSetAttribute(moe_gemm_kernel,
                         cudaFuncAttributeMaxDynamicSharedMemorySize, SMEM_BYTES);

    convert_w<<<(NE * DM * DH / 8) / 256, 256>>>((const float4*)ew);
    router_kernel<<<NT / 8, 256>>>(x, rw);

    dim3 grid(DH / BN, NT / BM, NE);           // (8, 64, 16), early-exit on cnt
    moe_gemm_kernel<<<grid, THREADS, SMEM_BYTES>>>();

    combine_kernel<<<(NT * DH / 4) / 256, 256>>>((float4*)out);
}